// round 10
// baseline (speedup 1.0000x reference)
#include <cuda_runtime.h>
#include <cuda_fp16.h>
#include <cstdint>

// ---------------- problem shapes ----------------
#define Bc   512
#define Sc   64
#define Nc   8
#define Ac   16
#define Hc   256
#define OBSc 512

// strides (32-bit words)
#define BSTR2 136    // uint32 words per B column (16 chunks * 8 + pad 8)
#define ATS   136    // uint32 words per staged A row in smem
#define AW    128    // uint32 words per A row in gmem

// ---------------- device scratch ----------------
__device__ __align__(16) uint32_t g_B16[2][128 * BSTR2];     // fp16x2 W2 image per n-half
__device__ __align__(16) float    g_PA2[Bc * 64 * 256];      // fp32 PA rows, obs folded u=0
__device__ __align__(16) uint32_t g_A[(size_t)Bc * 512 * AW];// fp16x2 A = mish(h1), frag layout

// ---------------- helpers ----------------
// mish(x) = x * (1 - 2/(u^2+1)), u = 1+e^x ; reciprocal via bit-hack + 2 Newton
__device__ __forceinline__ float mish_f(float x) {
    float e  = __expf(fminf(x, 15.0f));
    float u  = 1.0f + e;
    float d  = fmaf(u, u, 1.0f);                 // u^2 + 1  (>= 2)
    float r  = __uint_as_float(0x7EF477D5u - __float_as_uint(d));
    r = r * (2.0f - d * r);
    r = r * (2.0f - d * r);
    return x * (1.0f - 2.0f * r);
}
__device__ __forceinline__ uint32_t h2pack(float lo, float hi) {
    uint32_t r;
    asm("cvt.rn.f16x2.f32 %0, %1, %2;" : "=r"(r) : "f"(hi), "f"(lo));
    return r;
}

// m16n8k16 fp16 mma, f32 accumulate; C is a float4 variable (regs only)
#define MMA_F16(C, a0, a1, a2, a3, b0, b1)                                    \
    asm volatile("mma.sync.aligned.m16n8k16.row.col.f32.f16.f16.f32 "        \
        "{%0,%1,%2,%3}, {%4,%5,%6,%7}, {%8,%9}, {%0,%1,%2,%3};"              \
        : "+f"(C.x), "+f"(C.y), "+f"(C.z), "+f"(C.w)                         \
        : "r"(a0), "r"(a1), "r"(a2), "r"(a3), "r"(b0), "r"(b1))

// ================= prep 1: W2 -> fp16x2 packed B images =================
// per-column word: idx = chunk*8 + 2*kq + hi ; value = halves (k0, k0+1),
// k0 = chunk*16 + hi*8 + 2*kq
__global__ void prep_w2_kernel(const float* __restrict__ W2) {
    int idx = blockIdx.x * blockDim.x + threadIdx.x;   // 32768 words
    if (idx >= 2 * 128 * 128) return;
    int nhalf = idx >> 14;
    int rem   = idx & 16383;
    int col   = rem >> 7;
    int w     = rem & 127;
    int chunk = w >> 3;
    int kq    = (w >> 1) & 3;
    int hi    = w & 1;
    int k0    = chunk * 16 + hi * 8 + kq * 2;
    int n     = nhalf * 128 + col;
    g_B16[nhalf][col * BSTR2 + w] = h2pack(W2[k0 * Hc + n], W2[(k0 + 1) * Hc + n]);
}

// ================= prep 2: PA rows fp32 (obs folded into u=0) =================
__global__ void __launch_bounds__(256)
prep_obs_pa_kernel(const float* __restrict__ state,
                   const float* __restrict__ action,
                   const float* __restrict__ W1,
                   const float* __restrict__ b1) {
    __shared__ float sState[4 * OBSc];
    __shared__ float sAct[4 * 128];
    const int tid = threadIdx.x;
    const int b0  = blockIdx.x * 4;

    for (int i = tid; i < 4 * OBSc; i += 256) sState[i] = state[b0 * OBSc + i];
    for (int i = tid; i < 4 * 128;  i += 256) sAct[i]   = action[b0 * 128 + i];
    __syncthreads();

    const int h = tid;
    float ob0 = b1[h], ob1 = ob0, ob2 = ob0, ob3 = ob0;
    for (int k = 0; k < OBSc; ++k) {
        float w = __ldg(&W1[k * Hc + h]);
        ob0 = fmaf(sState[k],            w, ob0);
        ob1 = fmaf(sState[OBSc + k],     w, ob1);
        ob2 = fmaf(sState[2 * OBSc + k], w, ob2);
        ob3 = fmaf(sState[3 * OBSc + k], w, ob3);
    }

    for (int j = 0; j < 8; ++j) {
        for (int n = 0; n < 8; ++n) {
            float p0 = 0.f, p1 = 0.f, p2 = 0.f, p3 = 0.f;
            #pragma unroll
            for (int k = 0; k < 16; ++k) {
                float w = __ldg(&W1[(OBSc + j * 16 + k) * Hc + h]);
                p0 = fmaf(sAct[0 * 128 + n * 16 + k], w, p0);
                p1 = fmaf(sAct[1 * 128 + n * 16 + k], w, p1);
                p2 = fmaf(sAct[2 * 128 + n * 16 + k], w, p2);
                p3 = fmaf(sAct[3 * 128 + n * 16 + k], w, p3);
            }
            if (j == 0) { p0 += ob0; p1 += ob1; p2 += ob2; p3 += ob3; }
            g_PA2[((b0 + 0) * 64 + j * 8 + n) * 256 + h] = p0;
            g_PA2[((b0 + 1) * 64 + j * 8 + n) * 256 + h] = p1;
            g_PA2[((b0 + 2) * 64 + j * 8 + n) * 256 + h] = p2;
            g_PA2[((b0 + 3) * 64 + j * 8 + n) * 256 + h] = p3;
        }
    }
}

// ================= prep 3: full A = mish(prefix) fp16, fragment layout ========
// block = b (512 blocks, 256 threads). Row r = t*64 + s.
#define P3_SMEM (64 * 256 * 4 + 512 * 4)   // 67584 B
__global__ void __launch_bounds__(256)
prep_A_kernel(const int* __restrict__ perm) {
    extern __shared__ float p3s[];
    float* sPA   = p3s;                      // 64*256
    int*   sPerm = (int*)(p3s + 64 * 256);   // 512
    const int tid = threadIdx.x;
    const int b   = blockIdx.x;

    {
        const uint4* src = (const uint4*)(g_PA2 + (size_t)b * 64 * 256);
        uint4* dst = (uint4*)sPA;
        for (int i = tid; i < 4096; i += 256) dst[i] = src[i];
    }
    for (int i = tid; i < 512; i += 256) sPerm[i] = perm[b * 512 + i];
    __syncthreads();

    const int half = tid >> 7;       // 0/1 -> s blocks
    const int wp   = tid & 127;      // word position in A row
    const int ch   = wp >> 3;
    const int kq   = (wp >> 1) & 3;
    const int hi   = wp & 1;
    const int k0   = ch * 16 + hi * 8 + kq * 2;

    #pragma unroll 1
    for (int ss = 0; ss < 32; ++ss) {
        const int s = half * 32 + ss;
        float x0 = 0.f, x1 = 0.f;
        #pragma unroll
        for (int t = 0; t < 8; ++t) {
            const int row = t * 8 + sPerm[s * 8 + t];
            float2 v = *(const float2*)&sPA[row * 256 + k0];
            x0 += v.x; x1 += v.y;
            g_A[((size_t)b * 512 + t * 64 + s) * AW + wp] =
                h2pack(mish_f(x0), mish_f(x1));
        }
    }
}

// ================= main fused GEMM kernel =================
// grid 1024: (b = bx>>1, nh = bx&1). 256 threads, 8 warps, 2 CTAs/SM.
// 8 passes of 64 rows; warp tile 16 rows x 64 cols (rgrp = wid>>1, ch2 = wid&1).
#define OFF_B     0
#define SZ_B      (128 * BSTR2 * 4)        // 69632
#define OFF_A     (OFF_B + SZ_B)
#define SZ_A      (64 * ATS * 4)           // 34816
#define OFF_PERM  (OFF_A + SZ_A)           // 512 ints
#define OFF_ROWP  (OFF_PERM + 2048)        // 512*2 f
#define OFF_B2    (OFF_ROWP + 4096)        // 128 f
#define OFF_W3    (OFF_B2 + 512)           // 128 f
#define OFF_RED   (OFF_W3 + 512)           // 256 f
#define SMEM_MAIN (OFF_RED + 1024)         // 112640 B -> 2 CTAs/SM

__global__ void __launch_bounds__(256, 2)
shapley_mma(const float* __restrict__ b2,
            const float* __restrict__ W3,
            const float* __restrict__ b3,
            const int*   __restrict__ perm,
            float*       __restrict__ out) {
    extern __shared__ char smem[];
    const int tid  = threadIdx.x;
    const int wid  = tid >> 5;
    const int lane = tid & 31;
    const int b    = blockIdx.x >> 1;
    const int nh   = blockIdx.x & 1;

    uint32_t* sB  = (uint32_t*)(smem + OFF_B);
    uint32_t* sA  = (uint32_t*)(smem + OFF_A);
    int*   sPerm = (int*)  (smem + OFF_PERM);
    float* sRowP = (float*)(smem + OFF_ROWP);
    float* sB2   = (float*)(smem + OFF_B2);
    float* sW3   = (float*)(smem + OFF_W3);
    float* sRed  = (float*)(smem + OFF_RED);

    // ---- stage B ----
    {
        const uint4* src = (const uint4*)g_B16[nh];
        uint4* dst = (uint4*)sB;
        for (int i = tid; i < (128 * BSTR2) / 4; i += 256) dst[i] = src[i];
    }
    for (int i = tid; i < Sc * Nc; i += 256) sPerm[i] = perm[b * (Sc * Nc) + i];
    if (tid < 128) {
        sB2[tid] = b2[nh * 128 + tid];
        sW3[tid] = W3[nh * 128 + tid];
    }
    const float b3v = b3[0];

    const int lam  = lane >> 2;
    const int kq   = lane & 3;
    const int rgrp = wid >> 1;
    const int ch2  = wid & 1;
    const int rowa = rgrp * 16 + lam;          // A-tile row of frag rows (rowa, rowa+8)

    const uint4* aSrc = (const uint4*)(g_A + ((size_t)b * 512) * AW);
    // per-thread staging indices: element i = tid + j*256  (j = 0..7)
    // smem word addr = (i>>5)*ATS + (i&31)*4
    const int sr = tid >> 5, sc = tid & 31;    // j stride: +8 rows

    // prefetch tile 0 into named registers
    uint4 st0, st1, st2, st3, st4, st5, st6, st7;
#define LDG_TILE(p) { const uint4* s_ = aSrc + (size_t)(p) * (64 * 32) + tid;  \
    st0 = s_[0];     st1 = s_[256];  st2 = s_[512];  st3 = s_[768];            \
    st4 = s_[1024];  st5 = s_[1280]; st6 = s_[1536]; st7 = s_[1792]; }
#define STS_TILE() {                                                           \
    *(uint4*)&sA[(sr +  0) * ATS + sc * 4] = st0;                              \
    *(uint4*)&sA[(sr +  8) * ATS + sc * 4] = st1;                              \
    *(uint4*)&sA[(sr + 16) * ATS + sc * 4] = st2;                              \
    *(uint4*)&sA[(sr + 24) * ATS + sc * 4] = st3;                              \
    *(uint4*)&sA[(sr + 32) * ATS + sc * 4] = st4;                              \
    *(uint4*)&sA[(sr + 40) * ATS + sc * 4] = st5;                              \
    *(uint4*)&sA[(sr + 48) * ATS + sc * 4] = st6;                              \
    *(uint4*)&sA[(sr + 56) * ATS + sc * 4] = st7; }
    LDG_TILE(0);

    #pragma unroll 1
    for (int p = 0; p < 8; ++p) {
        __syncthreads();          // previous tile's readers done (and B/perm ready at p=0)
        STS_TILE();
        __syncthreads();          // tile visible
        if (p < 7) LDG_TILE(p + 1);   // prefetch next while computing

        float4 C0 = {0,0,0,0}, C1 = {0,0,0,0}, C2 = {0,0,0,0}, C3 = {0,0,0,0};
        float4 C4 = {0,0,0,0}, C5 = {0,0,0,0}, C6 = {0,0,0,0}, C7 = {0,0,0,0};

        #pragma unroll
        for (int ch = 0; ch < 16; ++ch) {
            const int aof = ch * 8 + 2 * kq;
            uint2 aLo = *(const uint2*)&sA[rowa * ATS + aof];         // a0 | a2
            uint2 aHi = *(const uint2*)&sA[(rowa + 8) * ATS + aof];   // a1 | a3
#define BMMA(nt) { uint2 bb = *(const uint2*)&sB[(((ch2 * 8 + nt) * 8) + lam) * BSTR2 + aof]; \
                   MMA_F16(C##nt, aLo.x, aHi.x, aLo.y, aHi.y, bb.x, bb.y); }
            BMMA(0) BMMA(1) BMMA(2) BMMA(3) BMMA(4) BMMA(5) BMMA(6) BMMA(7)
#undef BMMA
        }

        // ---- epilogue: mish(z+b2)*w3, row-sum over this warp's 64 cols ----
        float rs0 = 0.f, rs1 = 0.f;
#define EPI(nt) { const int c0 = ch2 * 64 + (nt) * 8 + kq * 2;                    \
    rs0 += mish_f(C##nt.x + sB2[c0])     * sW3[c0]                                \
         + mish_f(C##nt.y + sB2[c0 + 1]) * sW3[c0 + 1];                           \
    rs1 += mish_f(C##nt.z + sB2[c0])     * sW3[c0]                                \
         + mish_f(C##nt.w + sB2[c0 + 1]) * sW3[c0 + 1]; }
        EPI(0) EPI(1) EPI(2) EPI(3) EPI(4) EPI(5) EPI(6) EPI(7)
#undef EPI
        rs0 += __shfl_xor_sync(0xffffffffu, rs0, 1);
        rs0 += __shfl_xor_sync(0xffffffffu, rs0, 2);
        rs1 += __shfl_xor_sync(0xffffffffu, rs1, 1);
        rs1 += __shfl_xor_sync(0xffffffffu, rs1, 2);
        if (kq == 0) {
            sRowP[(p * 64 + rowa)     * 2 + ch2] = rs0;
            sRowP[(p * 64 + rowa + 8) * 2 + ch2] = rs1;
        }
    }
    __syncthreads();

    // ---- gather q1 partials: (s,i) -> row = perm[s,i]*64 + s ----
    {
        const int i = tid & 7, su = tid >> 3;
        int r0 = sPerm[su * 8 + i] * 64 + su;
        int r1 = sPerm[(su + 32) * 8 + i] * 64 + su + 32;
        sRed[tid] = sRowP[2 * r0] + sRowP[2 * r0 + 1]
                  + sRowP[2 * r1] + sRowP[2 * r1 + 1] + b3v;   // 0.5*b3 per row per CTA
    }
    __syncthreads();
    if (tid < 8) {
        float sum = 0.0f;
        #pragma unroll 8
        for (int g = 0; g < 32; ++g) sum += sRed[g * 8 + tid];
        atomicAdd(&out[b * Nc + tid], sum * (1.0f / 64.0f));
    }
}

// duplicate q1 into second half of the output tuple
__global__ void dup_out_kernel(float* __restrict__ out) {
    int i = blockIdx.x * blockDim.x + threadIdx.x;
    if (i < Bc * Nc) out[Bc * Nc + i] = out[i];
}

extern "C" void kernel_launch(void* const* d_in, const int* in_sizes, int n_in,
                              void* d_out, int out_size) {
    const float* state  = (const float*)d_in[0];
    const float* action = (const float*)d_in[1];
    const float* W1     = (const float*)d_in[2];
    const float* b1     = (const float*)d_in[3];
    const float* W2     = (const float*)d_in[4];
    const float* b2     = (const float*)d_in[5];
    const float* W3     = (const float*)d_in[6];
    const float* b3     = (const float*)d_in[7];
    const int*   perm   = (const int*)  d_in[8];
    float* out = (float*)d_out;

    cudaFuncSetAttribute(shapley_mma,
                         cudaFuncAttributeMaxDynamicSharedMemorySize, SMEM_MAIN);
    cudaFuncSetAttribute(prep_A_kernel,
                         cudaFuncAttributeMaxDynamicSharedMemorySize, P3_SMEM);

    prep_w2_kernel<<<128, 256>>>(W2);
    prep_obs_pa_kernel<<<128, 256>>>(state, action, W1, b1);
    prep_A_kernel<<<Bc, 256, P3_SMEM>>>(perm);

    int zelems = (out_size < Bc * Nc) ? out_size : (Bc * Nc);
    cudaMemsetAsync(d_out, 0, (size_t)zelems * sizeof(float), 0);

    shapley_mma<<<Bc * 2, 256, SMEM_MAIN>>>(b2, W3, b3, perm, out);

    if (out_size >= 2 * Bc * Nc)
        dup_out_kernel<<<(Bc * Nc + 255) / 256, 256>>>(out);
}

// round 11
// speedup vs baseline: 1.1115x; 1.1115x over previous
#include <cuda_runtime.h>
#include <cuda_fp16.h>
#include <cstdint>

// ---------------- problem shapes ----------------
#define Bc   512
#define Sc   64
#define Nc   8
#define Ac   16
#define Hc   256
#define OBSc 512

// strides (32-bit words)
#define BSTR2 136    // uint32 words per B column (16 chunks * 8 + pad 8)
#define ATS   136    // uint32 words per staged A row in smem
#define AW    128    // uint32 words per A row in gmem

// ---------------- device scratch ----------------
__device__ __align__(16) uint32_t g_B16[2][128 * BSTR2];      // fp16x2 W2 image per n-half
__device__ __align__(16) uint32_t g_A[(size_t)Bc * 512 * AW]; // fp16x2 A = mish(h1), frag layout

// ---------------- helpers ----------------
// mish(x) = x * (1 - 2/(u^2+1)), u = 1+e^x ; reciprocal via bit-hack + 2 Newton
__device__ __forceinline__ float mish_f(float x) {
    float e  = __expf(fminf(x, 15.0f));
    float u  = 1.0f + e;
    float d  = fmaf(u, u, 1.0f);                 // u^2 + 1  (>= 2)
    float r  = __uint_as_float(0x7EF477D5u - __float_as_uint(d));
    r = r * (2.0f - d * r);
    r = r * (2.0f - d * r);
    return x * (1.0f - 2.0f * r);
}
__device__ __forceinline__ uint32_t h2pack(float lo, float hi) {
    uint32_t r;
    asm("cvt.rn.f16x2.f32 %0, %1, %2;" : "=r"(r) : "f"(hi), "f"(lo));
    return r;
}

// m16n8k16 fp16 mma, f32 accumulate; C is a float4 variable (regs only)
#define MMA_F16(C, a0, a1, a2, a3, b0, b1)                                    \
    asm volatile("mma.sync.aligned.m16n8k16.row.col.f32.f16.f16.f32 "        \
        "{%0,%1,%2,%3}, {%4,%5,%6,%7}, {%8,%9}, {%0,%1,%2,%3};"              \
        : "+f"(C.x), "+f"(C.y), "+f"(C.z), "+f"(C.w)                         \
        : "r"(a0), "r"(a1), "r"(a2), "r"(a3), "r"(b0), "r"(b1))

// ================= prep 1: W2 -> fp16x2 packed B images =================
// per-column word: idx = chunk*8 + 2*kq + hi ; value = halves (k0, k0+1),
// k0 = chunk*16 + hi*8 + 2*kq
__global__ void prep_w2_kernel(const float* __restrict__ W2) {
    int idx = blockIdx.x * blockDim.x + threadIdx.x;   // 32768 words
    if (idx >= 2 * 128 * 128) return;
    int nhalf = idx >> 14;
    int rem   = idx & 16383;
    int col   = rem >> 7;
    int w     = rem & 127;
    int chunk = w >> 3;
    int kq    = (w >> 1) & 3;
    int hi    = w & 1;
    int k0    = chunk * 16 + hi * 8 + kq * 2;
    int n     = nhalf * 128 + col;
    g_B16[nhalf][col * BSTR2 + w] = h2pack(W2[k0 * Hc + n], W2[(k0 + 1) * Hc + n]);
}

// ================= merged prep: obs1 + PA (smem) -> A = mish(prefix) fp16 ====
// grid 512 (one b), 256 threads, 2 blocks/SM.
#define PB_SMEM ((512 + 128 + 64 * 256 + 512) * 4)   // 70144 B
__global__ void __launch_bounds__(256, 2)
prep_bA_kernel(const float* __restrict__ state,
               const float* __restrict__ action,
               const float* __restrict__ W1,
               const float* __restrict__ b1,
               const int*   __restrict__ perm) {
    extern __shared__ float pbs[];
    float* sState = pbs;                         // 512
    float* sAct   = pbs + 512;                   // 128
    float* sPA    = pbs + 640;                   // 64*256
    int*   sPerm  = (int*)(pbs + 640 + 64 * 256);// 512
    const int tid = threadIdx.x;
    const int b   = blockIdx.x;

    // stage inputs
    sState[tid]       = state[b * OBSc + tid];
    sState[256 + tid] = state[b * OBSc + 256 + tid];
    if (tid < 128) sAct[tid] = action[b * 128 + tid];
    for (int i = tid; i < 512; i += 256) sPerm[i] = perm[b * 512 + i];
    __syncthreads();

    // ---- obs1[h] (4-way split chain) ----
    const int h = tid;
    float oa = b1[h], obp = 0.f, oc = 0.f, od = 0.f;
    #pragma unroll 4
    for (int k = 0; k < OBSc; k += 4) {
        oa  = fmaf(sState[k],     __ldg(&W1[(k)     * Hc + h]), oa);
        obp = fmaf(sState[k + 1], __ldg(&W1[(k + 1) * Hc + h]), obp);
        oc  = fmaf(sState[k + 2], __ldg(&W1[(k + 2) * Hc + h]), oc);
        od  = fmaf(sState[k + 3], __ldg(&W1[(k + 3) * Hc + h]), od);
    }
    const float ob = (oa + obp) + (oc + od);

    // ---- PA rows into smem (obs folded into j=0) ----
    for (int j = 0; j < 8; ++j) {
        for (int n = 0; n < 8; ++n) {
            float p = (j == 0) ? ob : 0.0f;
            #pragma unroll
            for (int k = 0; k < 16; ++k)
                p = fmaf(sAct[n * 16 + k],
                         __ldg(&W1[(OBSc + j * 16 + k) * Hc + h]), p);
            sPA[(j * 8 + n) * 256 + h] = p;
        }
    }
    __syncthreads();

    // ---- prefix + mish + fp16 pack -> g_A (fragment word layout) ----
    const int half = tid >> 7;       // s block
    const int wp   = tid & 127;      // word position in A row
    const int ch   = wp >> 3;
    const int kq   = (wp >> 1) & 3;
    const int hi   = wp & 1;
    const int k0   = ch * 16 + hi * 8 + kq * 2;

    #pragma unroll 1
    for (int ss = 0; ss < 32; ++ss) {
        const int s = half * 32 + ss;
        float x0 = 0.f, x1 = 0.f;
        #pragma unroll
        for (int t = 0; t < 8; ++t) {
            const int row = t * 8 + sPerm[s * 8 + t];
            float2 v = *(const float2*)&sPA[row * 256 + k0];
            x0 += v.x; x1 += v.y;
            g_A[((size_t)b * 512 + t * 64 + s) * AW + wp] =
                h2pack(mish_f(x0), mish_f(x1));
        }
    }
}

// ================= main fused GEMM kernel =================
// grid 1024: (b = bx>>1, nh = bx&1). 256 threads, 8 warps, 2 CTAs/SM.
// 8 passes of 64 rows; warp tile 16 rows x 64 cols (rgrp = wid>>1, ch2 = wid&1).
#define OFF_B     0
#define SZ_B      (128 * BSTR2 * 4)        // 69632
#define OFF_A     (OFF_B + SZ_B)
#define SZ_A      (64 * ATS * 4)           // 34816
#define OFF_PERM  (OFF_A + SZ_A)           // 512 ints
#define OFF_ROWP  (OFF_PERM + 2048)        // 512*2 f
#define OFF_B2    (OFF_ROWP + 4096)        // 128 f
#define OFF_W3    (OFF_B2 + 512)           // 128 f
#define OFF_RED   (OFF_W3 + 512)           // 256 f
#define SMEM_MAIN (OFF_RED + 1024)         // 112640 B -> 2 CTAs/SM

__global__ void __launch_bounds__(256, 2)
shapley_mma(const float* __restrict__ b2,
            const float* __restrict__ W3,
            const float* __restrict__ b3,
            const int*   __restrict__ perm,
            float*       __restrict__ out) {
    extern __shared__ char smem[];
    const int tid  = threadIdx.x;
    const int wid  = tid >> 5;
    const int lane = tid & 31;
    const int b    = blockIdx.x >> 1;
    const int nh   = blockIdx.x & 1;

    uint32_t* sB  = (uint32_t*)(smem + OFF_B);
    uint32_t* sA  = (uint32_t*)(smem + OFF_A);
    int*   sPerm = (int*)  (smem + OFF_PERM);
    float* sRowP = (float*)(smem + OFF_ROWP);
    float* sB2   = (float*)(smem + OFF_B2);
    float* sW3   = (float*)(smem + OFF_W3);
    float* sRed  = (float*)(smem + OFF_RED);

    // ---- stage B ----
    {
        const uint4* src = (const uint4*)g_B16[nh];
        uint4* dst = (uint4*)sB;
        for (int i = tid; i < (128 * BSTR2) / 4; i += 256) dst[i] = src[i];
    }
    for (int i = tid; i < Sc * Nc; i += 256) sPerm[i] = perm[b * (Sc * Nc) + i];
    if (tid < 128) {
        sB2[tid] = b2[nh * 128 + tid];
        sW3[tid] = W3[nh * 128 + tid];
    }
    const float b3v = b3[0];

    const int lam  = lane >> 2;
    const int kq   = lane & 3;
    const int rgrp = wid >> 1;
    const int ch2  = wid & 1;
    const int rowa = rgrp * 16 + lam;          // A-tile row of frag rows (rowa, rowa+8)

    const uint4* aSrc = (const uint4*)(g_A + ((size_t)b * 512) * AW);
    const int sr = tid >> 5, sc = tid & 31;

    uint4 st0, st1, st2, st3, st4, st5, st6, st7;
#define LDG_TILE(p) { const uint4* s_ = aSrc + (size_t)(p) * (64 * 32) + tid;  \
    st0 = s_[0];     st1 = s_[256];  st2 = s_[512];  st3 = s_[768];            \
    st4 = s_[1024];  st5 = s_[1280]; st6 = s_[1536]; st7 = s_[1792]; }
#define STS_TILE() {                                                           \
    *(uint4*)&sA[(sr +  0) * ATS + sc * 4] = st0;                              \
    *(uint4*)&sA[(sr +  8) * ATS + sc * 4] = st1;                              \
    *(uint4*)&sA[(sr + 16) * ATS + sc * 4] = st2;                              \
    *(uint4*)&sA[(sr + 24) * ATS + sc * 4] = st3;                              \
    *(uint4*)&sA[(sr + 32) * ATS + sc * 4] = st4;                              \
    *(uint4*)&sA[(sr + 40) * ATS + sc * 4] = st5;                              \
    *(uint4*)&sA[(sr + 48) * ATS + sc * 4] = st6;                              \
    *(uint4*)&sA[(sr + 56) * ATS + sc * 4] = st7; }
    LDG_TILE(0);

    #pragma unroll 1
    for (int p = 0; p < 8; ++p) {
        __syncthreads();
        STS_TILE();
        __syncthreads();
        if (p < 7) LDG_TILE(p + 1);

        float4 C0 = {0,0,0,0}, C1 = {0,0,0,0}, C2 = {0,0,0,0}, C3 = {0,0,0,0};
        float4 C4 = {0,0,0,0}, C5 = {0,0,0,0}, C6 = {0,0,0,0}, C7 = {0,0,0,0};

        #pragma unroll
        for (int ch = 0; ch < 16; ++ch) {
            const int aof = ch * 8 + 2 * kq;
            uint2 aLo = *(const uint2*)&sA[rowa * ATS + aof];
            uint2 aHi = *(const uint2*)&sA[(rowa + 8) * ATS + aof];
#define BMMA(nt) { uint2 bb = *(const uint2*)&sB[(((ch2 * 8 + nt) * 8) + lam) * BSTR2 + aof]; \
                   MMA_F16(C##nt, aLo.x, aHi.x, aLo.y, aHi.y, bb.x, bb.y); }
            BMMA(0) BMMA(1) BMMA(2) BMMA(3) BMMA(4) BMMA(5) BMMA(6) BMMA(7)
#undef BMMA
        }

        float rs0 = 0.f, rs1 = 0.f;
#define EPI(nt) { const int c0 = ch2 * 64 + (nt) * 8 + kq * 2;                    \
    rs0 += mish_f(C##nt.x + sB2[c0])     * sW3[c0]                                \
         + mish_f(C##nt.y + sB2[c0 + 1]) * sW3[c0 + 1];                           \
    rs1 += mish_f(C##nt.z + sB2[c0])     * sW3[c0]                                \
         + mish_f(C##nt.w + sB2[c0 + 1]) * sW3[c0 + 1]; }
        EPI(0) EPI(1) EPI(2) EPI(3) EPI(4) EPI(5) EPI(6) EPI(7)
#undef EPI
        rs0 += __shfl_xor_sync(0xffffffffu, rs0, 1);
        rs0 += __shfl_xor_sync(0xffffffffu, rs0, 2);
        rs1 += __shfl_xor_sync(0xffffffffu, rs1, 1);
        rs1 += __shfl_xor_sync(0xffffffffu, rs1, 2);
        if (kq == 0) {
            sRowP[(p * 64 + rowa)     * 2 + ch2] = rs0;
            sRowP[(p * 64 + rowa + 8) * 2 + ch2] = rs1;
        }
    }
    __syncthreads();

    // ---- gather q1 partials: (s,i) -> row = perm[s,i]*64 + s ----
    {
        const int i = tid & 7, su = tid >> 3;
        int r0 = sPerm[su * 8 + i] * 64 + su;
        int r1 = sPerm[(su + 32) * 8 + i] * 64 + su + 32;
        sRed[tid] = sRowP[2 * r0] + sRowP[2 * r0 + 1]
                  + sRowP[2 * r1] + sRowP[2 * r1 + 1] + b3v;
    }
    __syncthreads();
    if (tid < 8) {
        float sum = 0.0f;
        #pragma unroll 8
        for (int g = 0; g < 32; ++g) sum += sRed[g * 8 + tid];
        float q = sum * (1.0f / 64.0f);
        atomicAdd(&out[b * Nc + tid], q);                 // q1
        atomicAdd(&out[Bc * Nc + b * Nc + tid], q);       // duplicate half
    }
}

extern "C" void kernel_launch(void* const* d_in, const int* in_sizes, int n_in,
                              void* d_out, int out_size) {
    const float* state  = (const float*)d_in[0];
    const float* action = (const float*)d_in[1];
    const float* W1     = (const float*)d_in[2];
    const float* b1     = (const float*)d_in[3];
    const float* W2     = (const float*)d_in[4];
    const float* b2     = (const float*)d_in[5];
    const float* W3     = (const float*)d_in[6];
    const float* b3     = (const float*)d_in[7];
    const int*   perm   = (const int*)  d_in[8];
    float* out = (float*)d_out;

    cudaFuncSetAttribute(shapley_mma,
                         cudaFuncAttributeMaxDynamicSharedMemorySize, SMEM_MAIN);
    cudaFuncSetAttribute(prep_bA_kernel,
                         cudaFuncAttributeMaxDynamicSharedMemorySize, PB_SMEM);

    prep_w2_kernel<<<128, 256>>>(W2);
    prep_bA_kernel<<<Bc, 256, PB_SMEM>>>(state, action, W1, b1, perm);

    int zelems = (out_size < 2 * Bc * Nc) ? out_size : (2 * Bc * Nc);
    cudaMemsetAsync(d_out, 0, (size_t)zelems * sizeof(float), 0);

    shapley_mma<<<Bc * 2, 256, SMEM_MAIN>>>(b2, W3, b3, perm, out);
}

// round 12
// speedup vs baseline: 1.1578x; 1.0417x over previous
#include <cuda_runtime.h>
#include <cuda_fp16.h>
#include <cstdint>

// ---------------- problem shapes ----------------
#define Bc   512
#define Sc   64
#define Nc   8
#define Ac   16
#define Hc   256
#define OBSc 512

// strides (32-bit words)
#define BSTR2 136    // uint32 words per B column (16 chunks * 8 + pad 8)
#define AW    128    // uint32 words per A row in gmem

// ---------------- device scratch ----------------
__device__ __align__(16) uint32_t g_B16[2][128 * BSTR2];      // fp16x2 W2 image per n-half
__device__ __align__(16) uint32_t g_A[(size_t)Bc * 512 * AW]; // fp16x2 A = mish(h1), frag layout

// ---------------- helpers ----------------
// mish(x) = x * (1 - 2/(u^2+1)), u = 1+e^x ; reciprocal via bit-hack + 2 Newton
__device__ __forceinline__ float mish_f(float x) {
    float e  = __expf(fminf(x, 15.0f));
    float u  = 1.0f + e;
    float d  = fmaf(u, u, 1.0f);                 // u^2 + 1  (>= 2)
    float r  = __uint_as_float(0x7EF477D5u - __float_as_uint(d));
    r = r * (2.0f - d * r);
    r = r * (2.0f - d * r);
    return x * (1.0f - 2.0f * r);
}
__device__ __forceinline__ uint32_t h2pack(float lo, float hi) {
    uint32_t r;
    asm("cvt.rn.f16x2.f32 %0, %1, %2;" : "=r"(r) : "f"(hi), "f"(lo));
    return r;
}

// m16n8k16 fp16 mma, f32 accumulate; C is a float4 variable (regs only)
#define MMA_F16(C, a0, a1, a2, a3, b0, b1)                                    \
    asm volatile("mma.sync.aligned.m16n8k16.row.col.f32.f16.f16.f32 "        \
        "{%0,%1,%2,%3}, {%4,%5,%6,%7}, {%8,%9}, {%0,%1,%2,%3};"              \
        : "+f"(C.x), "+f"(C.y), "+f"(C.z), "+f"(C.w)                         \
        : "r"(a0), "r"(a1), "r"(a2), "r"(a3), "r"(b0), "r"(b1))

// ================= prep 1: W2 -> fp16x2 packed B images =================
__global__ void prep_w2_kernel(const float* __restrict__ W2) {
    int idx = blockIdx.x * blockDim.x + threadIdx.x;   // 32768 words
    if (idx >= 2 * 128 * 128) return;
    int nhalf = idx >> 14;
    int rem   = idx & 16383;
    int col   = rem >> 7;
    int w     = rem & 127;
    int chunk = w >> 3;
    int kq    = (w >> 1) & 3;
    int hi    = w & 1;
    int k0    = chunk * 16 + hi * 8 + kq * 2;
    int n     = nhalf * 128 + col;
    g_B16[nhalf][col * BSTR2 + w] = h2pack(W2[k0 * Hc + n], W2[(k0 + 1) * Hc + n]);
}

// ================= merged prep: obs1 + PA (smem) -> A = mish(prefix) fp16 ====
// grid 512 (one b), 512 threads, 2 blocks/SM.
#define PB_SMEM ((512 + 128 + 512 + 64 * 256 + 512) * 4)   // 72192 B
__global__ void __launch_bounds__(512, 2)
prep_bA_kernel(const float* __restrict__ state,
               const float* __restrict__ action,
               const float* __restrict__ W1,
               const float* __restrict__ b1,
               const int*   __restrict__ perm) {
    extern __shared__ float pbs[];
    float* sState = pbs;                           // 512
    float* sAct   = pbs + 512;                     // 128
    float* sObsP  = pbs + 640;                     // 512 (2 partials x 256)
    float* sPA    = pbs + 1152;                    // 64*256
    int*   sPerm  = (int*)(pbs + 1152 + 64 * 256); // 512
    const int tid = threadIdx.x;
    const int b   = blockIdx.x;

    sState[tid] = state[b * OBSc + tid];
    if (tid < 128) sAct[tid] = action[b * 128 + tid];
    sPerm[tid] = perm[b * 512 + tid];
    __syncthreads();

    const int h   = tid & 255;
    const int seg = tid >> 8;                      // 0/1

    // ---- obs1 partial over this thread's k-half (4-way split chain) ----
    {
        float oa = 0.f, obp = 0.f, oc = 0.f, od = 0.f;
        const int kb = seg * 256;
        #pragma unroll 4
        for (int k = kb; k < kb + 256; k += 4) {
            oa  = fmaf(sState[k],     __ldg(&W1[(k)     * Hc + h]), oa);
            obp = fmaf(sState[k + 1], __ldg(&W1[(k + 1) * Hc + h]), obp);
            oc  = fmaf(sState[k + 2], __ldg(&W1[(k + 2) * Hc + h]), oc);
            od  = fmaf(sState[k + 3], __ldg(&W1[(k + 3) * Hc + h]), od);
        }
        sObsP[seg * 256 + h] = (oa + obp) + (oc + od) + (seg == 0 ? b1[h] : 0.f);
    }
    __syncthreads();
    const float ob = sObsP[h] + sObsP[256 + h];

    // ---- PA rows into smem; thread covers j in [seg*4, seg*4+4) ----
    #pragma unroll 1
    for (int jj = 0; jj < 4; ++jj) {
        const int j = seg * 4 + jj;
        #pragma unroll 1
        for (int n = 0; n < 8; ++n) {
            float p = (j == 0) ? ob : 0.0f;
            #pragma unroll
            for (int k = 0; k < 16; ++k)
                p = fmaf(sAct[n * 16 + k],
                         __ldg(&W1[(OBSc + j * 16 + k) * Hc + h]), p);
            sPA[(j * 8 + n) * 256 + h] = p;
        }
    }
    __syncthreads();

    // ---- prefix + mish + fp16 pack -> g_A (fragment word layout) ----
    const int quarter = tid >> 7;    // 0..3 -> s block of 16
    const int wp      = tid & 127;   // word position in A row
    const int ch      = wp >> 3;
    const int kq      = (wp >> 1) & 3;
    const int hi      = wp & 1;
    const int k0      = ch * 16 + hi * 8 + kq * 2;

    #pragma unroll 2
    for (int ss = 0; ss < 16; ++ss) {
        const int s = quarter * 16 + ss;
        float x0 = 0.f, x1 = 0.f;
        #pragma unroll
        for (int t = 0; t < 8; ++t) {
            const int row = t * 8 + sPerm[s * 8 + t];
            float2 v = *(const float2*)&sPA[row * 256 + k0];
            x0 += v.x; x1 += v.y;
            g_A[((size_t)b * 512 + t * 64 + s) * AW + wp] =
                h2pack(mish_f(x0), mish_f(x1));
        }
    }
}

// ================= main fused GEMM kernel =================
// grid 1024: (b = bx>>1, nh = bx&1). 256 threads, 8 warps, 2 CTAs/SM.
// Warp tile: 32 rows x 64 cols (rg = wid>>1, cg = wid&1); 4 passes of 128 rows.
// A fragments loaded directly from gmem (frag layout), B from smem.
#define OFF_B     0
#define SZ_B      (128 * BSTR2 * 4)        // 69632
#define OFF_PERM  (OFF_B + SZ_B)           // 512 ints
#define OFF_ROWP  (OFF_PERM + 2048)        // 512*2 f
#define OFF_B2    (OFF_ROWP + 4096)        // 128 f
#define OFF_W3    (OFF_B2 + 512)           // 128 f
#define OFF_RED   (OFF_W3 + 512)           // 256 f
#define SMEM_MAIN (OFF_RED + 1024)         // 77824 B -> 2 CTAs/SM

__global__ void __launch_bounds__(256, 2)
shapley_mma(const float* __restrict__ b2,
            const float* __restrict__ W3,
            const float* __restrict__ b3,
            const int*   __restrict__ perm,
            float*       __restrict__ out) {
    extern __shared__ char smem[];
    const int tid  = threadIdx.x;
    const int wid  = tid >> 5;
    const int lane = tid & 31;
    const int b    = blockIdx.x >> 1;
    const int nh   = blockIdx.x & 1;

    uint32_t* sB = (uint32_t*)(smem + OFF_B);
    int*   sPerm = (int*)  (smem + OFF_PERM);
    float* sRowP = (float*)(smem + OFF_ROWP);
    float* sB2   = (float*)(smem + OFF_B2);
    float* sW3   = (float*)(smem + OFF_W3);
    float* sRed  = (float*)(smem + OFF_RED);

    // ---- stage B (one-time) ----
    {
        const uint4* src = (const uint4*)g_B16[nh];
        uint4* dst = (uint4*)sB;
        for (int i = tid; i < (128 * BSTR2) / 4; i += 256) dst[i] = src[i];
    }
    for (int i = tid; i < Sc * Nc; i += 256) sPerm[i] = perm[b * (Sc * Nc) + i];
    if (tid < 128) {
        sB2[tid] = b2[nh * 128 + tid];
        sW3[tid] = W3[nh * 128 + tid];
    }
    const float b3v = b3[0];
    __syncthreads();

    const int lam = lane >> 2;
    const int kq  = lane & 3;
    const int rg  = wid >> 1;      // 0..3
    const int cg  = wid & 1;       // 0..1

    #pragma unroll 1
    for (int p = 0; p < 4; ++p) {
        const int r0 = p * 128 + rg * 32 + lam;
        const uint32_t* aR = g_A + ((size_t)b * 512 + r0) * AW + 2 * kq;

        float4 C0  = {0,0,0,0}, C1  = {0,0,0,0}, C2  = {0,0,0,0}, C3  = {0,0,0,0};
        float4 C4  = {0,0,0,0}, C5  = {0,0,0,0}, C6  = {0,0,0,0}, C7  = {0,0,0,0};
        float4 C8  = {0,0,0,0}, C9  = {0,0,0,0}, C10 = {0,0,0,0}, C11 = {0,0,0,0};
        float4 C12 = {0,0,0,0}, C13 = {0,0,0,0}, C14 = {0,0,0,0}, C15 = {0,0,0,0};

        // current A fragments (rows r0, r0+8, r0+16, r0+24), chunk 0
        uint2 a0 = *(const uint2*)(aR);
        uint2 a1 = *(const uint2*)(aR +  8 * AW);
        uint2 a2 = *(const uint2*)(aR + 16 * AW);
        uint2 a3 = *(const uint2*)(aR + 24 * AW);

        #pragma unroll
        for (int ch = 0; ch < 16; ++ch) {
            uint2 n0, n1, n2, n3;
            if (ch < 15) {                       // compile-time after unroll
                const int no = (ch + 1) * 8;
                n0 = *(const uint2*)(aR + no);
                n1 = *(const uint2*)(aR +  8 * AW + no);
                n2 = *(const uint2*)(aR + 16 * AW + no);
                n3 = *(const uint2*)(aR + 24 * AW + no);
            }
            const int bof = ch * 8 + 2 * kq;
#define BMMAQ(nt, nt8) { uint2 bb = *(const uint2*)&sB[((cg * 8 + (nt)) * 8 + lam) * BSTR2 + bof]; \
            MMA_F16(C##nt,  a0.x, a1.x, a0.y, a1.y, bb.x, bb.y);              \
            MMA_F16(C##nt8, a2.x, a3.x, a2.y, a3.y, bb.x, bb.y); }
            BMMAQ(0, 8) BMMAQ(1, 9) BMMAQ(2, 10) BMMAQ(3, 11)
            BMMAQ(4, 12) BMMAQ(5, 13) BMMAQ(6, 14) BMMAQ(7, 15)
#undef BMMAQ
            if (ch < 15) { a0 = n0; a1 = n1; a2 = n2; a3 = n3; }
        }

        // ---- epilogue: mish(z+b2)*w3, row-sums for 4 rows ----
        float rs0 = 0.f, rs1 = 0.f, rs2 = 0.f, rs3 = 0.f;
#define EPI2(nt, nt8) { const int c0i = cg * 64 + (nt) * 8 + kq * 2;              \
    const float w0 = sW3[c0i], w1 = sW3[c0i + 1];                                 \
    const float z0 = sB2[c0i], z1 = sB2[c0i + 1];                                 \
    rs0 += mish_f(C##nt.x  + z0) * w0 + mish_f(C##nt.y  + z1) * w1;               \
    rs1 += mish_f(C##nt.z  + z0) * w0 + mish_f(C##nt.w  + z1) * w1;               \
    rs2 += mish_f(C##nt8.x + z0) * w0 + mish_f(C##nt8.y + z1) * w1;               \
    rs3 += mish_f(C##nt8.z + z0) * w0 + mish_f(C##nt8.w + z1) * w1; }
        EPI2(0, 8) EPI2(1, 9) EPI2(2, 10) EPI2(3, 11)
        EPI2(4, 12) EPI2(5, 13) EPI2(6, 14) EPI2(7, 15)
#undef EPI2
        rs0 += __shfl_xor_sync(0xffffffffu, rs0, 1);
        rs0 += __shfl_xor_sync(0xffffffffu, rs0, 2);
        rs1 += __shfl_xor_sync(0xffffffffu, rs1, 1);
        rs1 += __shfl_xor_sync(0xffffffffu, rs1, 2);
        rs2 += __shfl_xor_sync(0xffffffffu, rs2, 1);
        rs2 += __shfl_xor_sync(0xffffffffu, rs2, 2);
        rs3 += __shfl_xor_sync(0xffffffffu, rs3, 1);
        rs3 += __shfl_xor_sync(0xffffffffu, rs3, 2);
        if (kq == 0) {
            sRowP[(r0)      * 2 + cg] = rs0;
            sRowP[(r0 +  8) * 2 + cg] = rs1;
            sRowP[(r0 + 16) * 2 + cg] = rs2;
            sRowP[(r0 + 24) * 2 + cg] = rs3;
        }
    }
    __syncthreads();

    // ---- gather q1 partials: (s,i) -> row = perm[s,i]*64 + s ----
    {
        const int i = tid & 7, su = tid >> 3;
        int r0 = sPerm[su * 8 + i] * 64 + su;
        int r1 = sPerm[(su + 32) * 8 + i] * 64 + su + 32;
        sRed[tid] = sRowP[2 * r0] + sRowP[2 * r0 + 1]
                  + sRowP[2 * r1] + sRowP[2 * r1 + 1] + b3v;
    }
    __syncthreads();
    if (tid < 8) {
        float sum = 0.0f;
        #pragma unroll 8
        for (int g = 0; g < 32; ++g) sum += sRed[g * 8 + tid];
        float q = sum * (1.0f / 64.0f);
        atomicAdd(&out[b * Nc + tid], q);                 // q1
        atomicAdd(&out[Bc * Nc + b * Nc + tid], q);       // duplicate half
    }
}

extern "C" void kernel_launch(void* const* d_in, const int* in_sizes, int n_in,
                              void* d_out, int out_size) {
    const float* state  = (const float*)d_in[0];
    const float* action = (const float*)d_in[1];
    const float* W1     = (const float*)d_in[2];
    const float* b1     = (const float*)d_in[3];
    const float* W2     = (const float*)d_in[4];
    const float* b2     = (const float*)d_in[5];
    const float* W3     = (const float*)d_in[6];
    const float* b3     = (const float*)d_in[7];
    const int*   perm   = (const int*)  d_in[8];
    float* out = (float*)d_out;

    cudaFuncSetAttribute(shapley_mma,
                         cudaFuncAttributeMaxDynamicSharedMemorySize, SMEM_MAIN);
    cudaFuncSetAttribute(prep_bA_kernel,
                         cudaFuncAttributeMaxDynamicSharedMemorySize, PB_SMEM);

    prep_w2_kernel<<<128, 256>>>(W2);
    prep_bA_kernel<<<Bc, 512, PB_SMEM>>>(state, action, W1, b1, perm);

    int zelems = (out_size < 2 * Bc * Nc) ? out_size : (2 * Bc * Nc);
    cudaMemsetAsync(d_out, 0, (size_t)zelems * sizeof(float), 0);

    shapley_mma<<<Bc * 2, 256, SMEM_MAIN>>>(b2, W3, b3, perm, out);
}